// round 16
// baseline (speedup 1.0000x reference)
#include <cuda_runtime.h>

#define VOCAB 100000
#define EE 128
#define SS 512

// per-vocab table: (e, e*m0, e*m1, pad), 1.6 MB — L2-resident
__device__ float4 g_tbl[VOCAB];

// ---------------- K1: vocab sweep ----------------
// 512 threads = 16 warps; each 8-lane subgroup owns one row (4 rows/warp,
// 64 rows/block). grid = ceil(100000/64) = 1563.
__global__ __launch_bounds__(512, 2)
void vocab_kernel(const float* __restrict__ emb,
                  const float* __restrict__ Wq,
                  const float* __restrict__ bq,
                  const float* __restrict__ Wm,
                  float4* __restrict__ tbl)
{
    const int tid = threadIdx.x;
    const int w  = tid >> 5;
    const int l  = tid & 31;
    const int sg = l >> 3;
    const int j  = l & 7;

    // lane's element slots: e = 4*(j+8k) + {0..3}, k = 0..3
    float4 wq[4], wma[4], wmb[4];
    #pragma unroll
    for (int k = 0; k < 4; k++) {
        wq[k]  = reinterpret_cast<const float4*>(Wq)[j + 8 * k];
        wma[k] = reinterpret_cast<const float4*>(Wm)[2 * (j + 8 * k)];     // (m0,m1) of e0,e1
        wmb[k] = reinterpret_cast<const float4*>(Wm)[2 * (j + 8 * k) + 1]; // (m0,m1) of e2,e3
    }
    const float bq0 = bq[0];

    const int v = blockIdx.x * 64 + w * 4 + sg;
    if (v >= VOCAB) return;
    const float* row = emb + (size_t)v * EE;

    float4 r[4];
    #pragma unroll
    for (int k = 0; k < 4; k++)
        r[k] = reinterpret_cast<const float4*>(row)[j + 8 * k];

    float dq = 0.f, sm = 0.f, d0 = 0.f, d1 = 0.f;
    #pragma unroll
    for (int k = 0; k < 4; k++) {
        dq += r[k].x * wq[k].x + r[k].y * wq[k].y + r[k].z * wq[k].z + r[k].w * wq[k].w;
        sm += (r[k].x + r[k].y) + (r[k].z + r[k].w);
        d0 += r[k].x * wma[k].x + r[k].y * wma[k].z + r[k].z * wmb[k].x + r[k].w * wmb[k].z;
        d1 += r[k].x * wma[k].y + r[k].y * wma[k].w + r[k].z * wmb[k].y + r[k].w * wmb[k].w;
    }
    #pragma unroll
    for (int o = 4; o; o >>= 1) {                  // 3-level butterfly within subgroup
        dq += __shfl_xor_sync(0xffffffffu, dq, o);
        sm += __shfl_xor_sync(0xffffffffu, sm, o);
        d0 += __shfl_xor_sync(0xffffffffu, d0, o);
        d1 += __shfl_xor_sync(0xffffffffu, d1, o);
    }
    if (j == 0) {
        // |lp| << 1: exp without max-subtraction is numerically safe (validated R8+)
        const float e = __expf((dq + bq0) * sm);
        tbl[v] = make_float4(e, e * d0, e * d1, 0.f);
    }
}

// ---------------- K2: per-batch-row reduce + head ----------------
__global__ __launch_bounds__(SS, 2)
void batch_kernel(const int* __restrict__ x,
                  const float4* __restrict__ tbl,
                  const float* __restrict__ bm,
                  float* __restrict__ out)
{
    __shared__ float s_red[16][4];

    const int b   = blockIdx.x;
    const int tid = threadIdx.x;
    const int w   = tid >> 5;
    const int l   = tid & 31;

    const float4 t = tbl[x[b * SS + tid]];         // one 16B L2-hit gather per token
    float Z = t.x, a0 = t.y, a1 = t.z;

    #pragma unroll
    for (int o = 16; o; o >>= 1) {
        Z  += __shfl_xor_sync(0xffffffffu, Z,  o);
        a0 += __shfl_xor_sync(0xffffffffu, a0, o);
        a1 += __shfl_xor_sync(0xffffffffu, a1, o);
    }
    if (l == 0) {
        s_red[w][0] = Z;
        s_red[w][1] = a0;
        s_red[w][2] = a1;
    }
    __syncthreads();
    if (w == 0) {
        float z = (l < 16) ? s_red[l][0] : 0.f;
        float u = (l < 16) ? s_red[l][1] : 0.f;
        float v = (l < 16) ? s_red[l][2] : 0.f;
        #pragma unroll
        for (int o = 8; o; o >>= 1) {
            z += __shfl_xor_sync(0xffffffffu, z, o);
            u += __shfl_xor_sync(0xffffffffu, u, o);
            v += __shfl_xor_sync(0xffffffffu, v, o);
        }
        if (l == 0) {
            const float inv = 1.0f / z;
            out[b * 2 + 0] = fmaxf(fmaf(u, inv, bm[0]), 0.f);
            out[b * 2 + 1] = fmaxf(fmaf(v, inv, bm[1]), 0.f);
        }
    }
}

extern "C" void kernel_launch(void* const* d_in, const int* in_sizes, int n_in,
                              void* d_out, int out_size)
{
    const int*   x   = (const int*)  d_in[0];
    const float* emb = (const float*)d_in[1];
    const float* Wq  = (const float*)d_in[2];
    const float* bq  = (const float*)d_in[3];
    const float* Wm  = (const float*)d_in[4];
    const float* bm  = (const float*)d_in[5];
    float* out = (float*)d_out;

    float4* tbl;
    cudaGetSymbolAddress((void**)&tbl, g_tbl);

    vocab_kernel<<<(VOCAB + 63) / 64, 512>>>(emb, Wq, bq, Wm, tbl);
    batch_kernel<<<256, SS>>>(x, tbl, bm, out);
}

// round 17
// speedup vs baseline: 1.2972x; 1.2972x over previous
#include <cuda_runtime.h>

#define VOCAB 100000
#define EE 128
#define SS 512

#define K1_BLOCKS 296            // 2 per SM, persistent
#define K1_ROWS_PER_ITER (K1_BLOCKS * 64)

// per-vocab table: (e, e*m0, e*m1, pad), 1.6 MB — L2-resident
__device__ float4 g_tbl[VOCAB];

// ---------------- K1: persistent vocab sweep ----------------
// 512 threads = 16 warps. 16-lane subgroup owns one row; 2 rows per subgroup
// per iteration -> 64 rows per block-iteration. Weight cache = 24 regs.
__global__ __launch_bounds__(512, 2)
void vocab_kernel(const float* __restrict__ emb,
                  const float* __restrict__ Wq,
                  const float* __restrict__ bq,
                  const float* __restrict__ Wm,
                  float4* __restrict__ tbl)
{
    const int tid = threadIdx.x;
    const int w = tid >> 5;
    const int l = tid & 31;
    const int h = l >> 4;        // 16-lane subgroup 0/1
    const int j = l & 15;

    // lane's float4 slots within a row: j and j+16  (row = 32 float4 slots)
    // Wm is [E,2] row-major: float4 slot s covers Wm float4s 2s and 2s+1
    float4 wq[2], wma[2], wmb[2];
    #pragma unroll
    for (int k = 0; k < 2; k++) {
        const int s = j + 16 * k;
        wq[k]  = reinterpret_cast<const float4*>(Wq)[s];
        wma[k] = reinterpret_cast<const float4*>(Wm)[2 * s];      // (m0,m1) e0,e1
        wmb[k] = reinterpret_cast<const float4*>(Wm)[2 * s + 1];  // (m0,m1) e2,e3
    }
    const float bq0 = bq[0];
    const float4* emb4 = reinterpret_cast<const float4*>(emb);

    for (int base = blockIdx.x * 64; base < VOCAB; base += K1_ROWS_PER_ITER) {
        const int v0 = base + w * 4 + h * 2;      // this subgroup's 2 rows

        float dq[2], sm[2], d0[2], d1[2];
        float4 r[2][2];

        #pragma unroll
        for (int t = 0; t < 2; t++) {
            const int v = v0 + t;
            const bool ok = (v < VOCAB);
            const size_t rb = (size_t)(ok ? v : 0) * 32;
            #pragma unroll
            for (int k = 0; k < 2; k++)
                r[t][k] = emb4[rb + j + 16 * k];

            dq[t] = 0.f; sm[t] = 0.f; d0[t] = 0.f; d1[t] = 0.f;
            #pragma unroll
            for (int k = 0; k < 2; k++) {
                dq[t] += r[t][k].x * wq[k].x + r[t][k].y * wq[k].y
                       + r[t][k].z * wq[k].z + r[t][k].w * wq[k].w;
                sm[t] += (r[t][k].x + r[t][k].y) + (r[t][k].z + r[t][k].w);
                d0[t] += r[t][k].x * wma[k].x + r[t][k].y * wma[k].z
                       + r[t][k].z * wmb[k].x + r[t][k].w * wmb[k].z;
                d1[t] += r[t][k].x * wma[k].y + r[t][k].y * wma[k].w
                       + r[t][k].z * wmb[k].y + r[t][k].w * wmb[k].w;
            }
        }
        // 4-level butterfly within 16-lane subgroup; 8 interleaved chains (ILP)
        #pragma unroll
        for (int o = 8; o; o >>= 1) {
            #pragma unroll
            for (int t = 0; t < 2; t++) {
                dq[t] += __shfl_xor_sync(0xffffffffu, dq[t], o);
                sm[t] += __shfl_xor_sync(0xffffffffu, sm[t], o);
                d0[t] += __shfl_xor_sync(0xffffffffu, d0[t], o);
                d1[t] += __shfl_xor_sync(0xffffffffu, d1[t], o);
            }
        }
        if (j == 0) {
            #pragma unroll
            for (int t = 0; t < 2; t++) {
                const int v = v0 + t;
                if (v < VOCAB) {
                    // |lp| << 1: exp without max-subtraction is safe (validated R8+)
                    const float e = __expf((dq[t] + bq0) * sm[t]);
                    tbl[v] = make_float4(e, e * d0[t], e * d1[t], 0.f);
                }
            }
        }
    }
}

// ---------------- K2: per-batch-row reduce + head (single wave) ----------------
// grid 128, 512 threads: half-block (8 warps) per batch row, 2 tokens/thread.
__global__ __launch_bounds__(512, 2)
void batch_kernel(const int* __restrict__ x,
                  const float4* __restrict__ tbl,
                  const float* __restrict__ bm,
                  float* __restrict__ out)
{
    __shared__ float s_red[16][4];

    const int tid  = threadIdx.x;
    const int w    = tid >> 5;
    const int l    = tid & 31;
    const int half = tid >> 8;                    // 0: warps 0-7, 1: warps 8-15
    const int ht   = tid & 255;
    const int b    = blockIdx.x * 2 + half;

    const int2 xx = reinterpret_cast<const int2*>(x + (size_t)b * SS)[ht];
    const float4 t0 = tbl[xx.x];
    const float4 t1 = tbl[xx.y];
    float Z  = t0.x + t1.x;
    float a0 = t0.y + t1.y;
    float a1 = t0.z + t1.z;

    #pragma unroll
    for (int o = 16; o; o >>= 1) {
        Z  += __shfl_xor_sync(0xffffffffu, Z,  o);
        a0 += __shfl_xor_sync(0xffffffffu, a0, o);
        a1 += __shfl_xor_sync(0xffffffffu, a1, o);
    }
    if (l == 0) {
        s_red[w][0] = Z;
        s_red[w][1] = a0;
        s_red[w][2] = a1;
    }
    __syncthreads();
    // warp 0 finishes row b0 (partials 0-7), warp 8 finishes row b1 (8-15)
    if ((w & 7) == 0) {
        const int pb = (w >> 3) * 8;
        float z = (l < 8) ? s_red[pb + l][0] : 0.f;
        float u = (l < 8) ? s_red[pb + l][1] : 0.f;
        float v = (l < 8) ? s_red[pb + l][2] : 0.f;
        #pragma unroll
        for (int o = 4; o; o >>= 1) {
            z += __shfl_xor_sync(0xffffffffu, z, o);
            u += __shfl_xor_sync(0xffffffffu, u, o);
            v += __shfl_xor_sync(0xffffffffu, v, o);
        }
        if (l == 0) {
            const int bb = blockIdx.x * 2 + (w >> 3);
            const float inv = 1.0f / z;
            out[bb * 2 + 0] = fmaxf(fmaf(u, inv, bm[0]), 0.f);
            out[bb * 2 + 1] = fmaxf(fmaf(v, inv, bm[1]), 0.f);
        }
    }
}

extern "C" void kernel_launch(void* const* d_in, const int* in_sizes, int n_in,
                              void* d_out, int out_size)
{
    const int*   x   = (const int*)  d_in[0];
    const float* emb = (const float*)d_in[1];
    const float* Wq  = (const float*)d_in[2];
    const float* bq  = (const float*)d_in[3];
    const float* Wm  = (const float*)d_in[4];
    const float* bm  = (const float*)d_in[5];
    float* out = (float*)d_out;

    float4* tbl;
    cudaGetSymbolAddress((void**)&tbl, g_tbl);

    vocab_kernel<<<K1_BLOCKS, 512>>>(emb, Wq, bq, Wm, tbl);
    batch_kernel<<<128, 512>>>(x, tbl, bm, out);
}